// round 6
// baseline (speedup 1.0000x reference)
#include <cuda_runtime.h>
#include <math.h>
#include <stdint.h>

#define Nn   4096
#define Tt   2048
#define Dd   256
#define H1d  128
#define H2d  32
#define NHd  4
#define CAP  96
#define LRELU_ALPHA 0.2f

// ------------------------- scratch (__device__ globals) --------------------
__device__ float g_Wh_c[NHd * Nn * Dd];
__device__ float g_Wh_t[NHd * Tt * Dd];
__device__ float g_f_c[NHd * Nn], g_g_c[NHd * Nn];
__device__ float g_f_t[NHd * Tt], g_g_t[NHd * Tt];
__device__ int   g_nbr_c[Nn * CAP];
__device__ float g_val_c[Nn * CAP];
__device__ int   g_cnt_c[Nn];
__device__ int   g_nbr_t[Tt * CAP];
__device__ float g_val_t[Tt * CAP];
__device__ int   g_cnt_t[Tt];
__device__ float g_concept[Nn * Dd];
__device__ float g_ctext[Nn * Dd];
__device__ float g_tmp1[Nn * H1d];
__device__ float g_h1[Nn * H1d];
__device__ float g_tmp2a[Nn * H2d];
__device__ float g_tmp2b[Nn * H2d];
// hi/lo planes (A operands: m-major; B operands: n-major [N,K])
__device__ float g_x_h[Nn * Dd],        g_x_l[Nn * Dd];
__device__ float g_tx_h[Tt * Dd],       g_tx_l[Tt * Dd];
__device__ float g_tf_h[Tt * Nn],       g_tf_l[Tt * Nn];
__device__ float g_gatWT_h[NHd * Dd * Dd], g_gatWT_l[NHd * Dd * Dd];
__device__ float g_tWT_h[NHd * Dd * Dd],   g_tWT_l[NHd * Dd * Dd];
__device__ float g_fcWcT_h[NHd * Dd * Dd], g_fcWcT_l[NHd * Dd * Dd];
__device__ float g_fcWtT_h[NHd * Dd * Dd], g_fcWtT_l[NHd * Dd * Dd];
__device__ float g_fusWT_h[Dd * Dd],    g_fusWT_l[Dd * Dd];
__device__ float g_gc1WT_h[Dd * H1d],   g_gc1WT_l[Dd * H1d];
__device__ float g_hcatc_h[Nn * NHd * Dd], g_hcatc_l[Nn * NHd * Dd];
__device__ float g_hcatt_h[Tt * NHd * Dd], g_hcatt_l[Tt * NHd * Dd];
__device__ float g_gtextT_h[Tt * Dd],   g_gtextT_l[Tt * Dd];   // [D, T]
__device__ float g_fused_h[Nn * Dd],    g_fused_l[Nn * Dd];
__device__ float g_fusion_h[Nn * Dd],   g_fusion_l[Nn * Dd];
__device__ float g_mu_h[Nn * H2d],      g_mu_l[Nn * H2d];

// ------------------------- tf32 helpers ------------------------------------
__device__ __forceinline__ void tf32_split_u(float v, uint32_t& h, uint32_t& l) {
    asm("cvt.rna.tf32.f32 %0, %1;" : "=r"(h) : "f"(v));
    float r = v - __uint_as_float(h);
    asm("cvt.rna.tf32.f32 %0, %1;" : "=r"(l) : "f"(r));
}
__device__ __forceinline__ void split_store(float v, float* hp, float* lp, size_t idx) {
    uint32_t h, l; tf32_split_u(v, h, l);
    hp[idx] = __uint_as_float(h); lp[idx] = __uint_as_float(l);
}

#define MMA_TF32(c, a, b)                                                         \
    asm volatile(                                                                  \
        "mma.sync.aligned.m16n8k8.row.col.f32.tf32.tf32.f32 "                      \
        "{%0,%1,%2,%3},{%4,%5,%6,%7},{%8,%9},{%0,%1,%2,%3};"                       \
        : "+f"((c)[0]), "+f"((c)[1]), "+f"((c)[2]), "+f"((c)[3])                   \
        : "r"((a)[0]), "r"((a)[1]), "r"((a)[2]), "r"((a)[3]),                      \
          "r"((b)[0]), "r"((b)[1]))

#define LDSM4(r0, r1, r2, r3, addr)                                                \
    asm volatile("ldmatrix.sync.aligned.m8n8.x4.shared.b16 {%0,%1,%2,%3}, [%4];"   \
        : "=r"(r0), "=r"(r1), "=r"(r2), "=r"(r3) : "r"(addr))

__device__ __forceinline__ void cp16(void* sp, const void* gp) {
    uint32_t s = (uint32_t)__cvta_generic_to_shared(sp);
    asm volatile("cp.async.cg.shared.global [%0], [%1], 16;" :: "r"(s), "l"(gp));
}

// ------------------------- split (no transpose): x, t_x, tfidf -------------
struct SplitJob { const float* src; float* hi; float* lo; int n4; };
struct SplitJobs3 { SplitJob j[3]; };
__global__ void split_all_kernel(SplitJobs3 jobs) {
    SplitJob jb = jobs.j[blockIdx.y];
    const float4* src = (const float4*)jb.src;
    float4* hi = (float4*)jb.hi;
    float4* lo = (float4*)jb.lo;
    for (int i = blockIdx.x * blockDim.x + threadIdx.x; i < jb.n4;
         i += gridDim.x * blockDim.x) {
        float4 v = src[i];
        uint32_t h, l;
        float4 vh, vl;
        tf32_split_u(v.x, h, l); vh.x = __uint_as_float(h); vl.x = __uint_as_float(l);
        tf32_split_u(v.y, h, l); vh.y = __uint_as_float(h); vl.y = __uint_as_float(l);
        tf32_split_u(v.z, h, l); vh.z = __uint_as_float(h); vl.z = __uint_as_float(l);
        tf32_split_u(v.w, h, l); vh.w = __uint_as_float(h); vl.w = __uint_as_float(l);
        hi[i] = vh; lo[i] = vl;
    }
}

// ------------------------- transpose+split: weights [K,N] -> [N,K] ---------
struct TJob { const float* src; float* hi; float* lo; int K; int N; int batch; };
struct TJobs6 { TJob j[6]; };
__global__ void transpose_split_kernel(TJobs6 jobs) {
    TJob jb = jobs.j[blockIdx.y];
    int b = blockIdx.z;
    if (b >= jb.batch) return;
    size_t stride = (size_t)jb.K * jb.N;
    const float* src = jb.src + b * stride;
    float* hi = jb.hi + b * stride;
    float* lo = jb.lo + b * stride;
    __shared__ float th[32][33], tl[32][33];
    int ntn = jb.N / 32, ntk = jb.K / 32;
    for (int tile = blockIdx.x; tile < ntn * ntk; tile += gridDim.x) {
        int tk = tile / ntn, tn = tile - tk * ntn;
        int k0 = tk * 32, n0 = tn * 32;
        #pragma unroll
        for (int i = 0; i < 4; i++) {
            int k = threadIdx.y + i * 8;
            float v = src[(size_t)(k0 + k) * jb.N + n0 + threadIdx.x];
            uint32_t h, l; tf32_split_u(v, h, l);
            th[k][threadIdx.x] = __uint_as_float(h);
            tl[k][threadIdx.x] = __uint_as_float(l);
        }
        __syncthreads();
        #pragma unroll
        for (int i = 0; i < 4; i++) {
            int n = threadIdx.y + i * 8;
            hi[(size_t)(n0 + n) * jb.K + k0 + threadIdx.x] = th[threadIdx.x][n];
            lo[(size_t)(n0 + n) * jb.K + k0 + threadIdx.x] = tl[threadIdx.x][n];
        }
        __syncthreads();
    }
}

// ------------------------- CSR build: two-pass warp-strip ------------------
__global__ void build_csr_kernel(const float* __restrict__ adj, int n,
                                 int* __restrict__ nbr, float* __restrict__ val,
                                 int* __restrict__ cnt) {
    int i = blockIdx.x;
    const float* row = adj + (size_t)i * n;
    int t = threadIdx.x, lane = t & 31, w = t >> 5;
    int strip = n >> 3;
    int s0 = w * strip;
    __shared__ int s_cnt[8];
    int my = 0;
    for (int b = s0; b < s0 + strip; b += 32) {
        bool p = row[b + lane] > 0.0f;
        unsigned m = __ballot_sync(0xffffffffu, p);
        my += __popc(m);
    }
    if (lane == 0) s_cnt[w] = my;
    __syncthreads();
    int off = 0;
    #pragma unroll
    for (int ww = 0; ww < 8; ww++) if (ww < w) off += s_cnt[ww];
    int tot = 0;
    #pragma unroll
    for (int ww = 0; ww < 8; ww++) tot += s_cnt[ww];
    for (int b = s0; b < s0 + strip; b += 32) {
        float v = row[b + lane];
        bool p = v > 0.0f;
        unsigned m = __ballot_sync(0xffffffffu, p);
        int pos = off + __popc(m & ((1u << lane) - 1u));
        if (p && pos < CAP) { nbr[i * CAP + pos] = b + lane; val[i * CAP + pos] = v; }
        off += __popc(m);
    }
    if (t == 0) cnt[i] = min(tot, CAP);
}

// ------------------------- tensor-core GEMM, ldmatrix fragments ------------
// C = op(A) @ B^T(+bias); A planes: TA ? [K,M] : [M,K]; B planes: ALWAYS [N,K].
// M%128==0, N%64==0, K%32==0. 3-stage cp.async pipeline.
#define BMt 128
#define BNt 64
#define BKt 16

template <bool TA>
__global__ void __launch_bounds__(256, 2) mma_gemm_kernel(
    const float* __restrict__ Ah, const float* __restrict__ Al,
    const float* __restrict__ Bh, const float* __restrict__ Bl,
    const float* __restrict__ bias, float* __restrict__ C,
    float* __restrict__ Ch, float* __restrict__ Cl, int transC,
    int M, int N, int K, size_t sA, size_t sB, size_t sC) {
    constexpr int AR = TA ? BKt : BMt;
    constexpr int AC = TA ? (BMt + 8) : (BKt + 4);
    constexpr int BC = BKt + 4;
    __shared__ float As[3][2][AR][AC];
    __shared__ float Bs[3][2][BNt][BC];

    const float* Abp[2] = { Ah + (size_t)blockIdx.z * sA, Al + (size_t)blockIdx.z * sA };
    const float* Bbp[2] = { Bh + (size_t)blockIdx.z * sB, Bl + (size_t)blockIdx.z * sB };
    int bm = blockIdx.y * BMt, bn = blockIdx.x * BNt;
    int t = threadIdx.x, lane = t & 31, w = t >> 5;
    int wm = (w & 3) * 32, wn = (w >> 2) * 32;
    int gid = lane >> 2, tig = lane & 3;

    float acc[2][4][4] = {};

    // ldmatrix per-thread offsets (bytes, relative to plane base)
    uint32_t a_off[2], b_off[2];
    #pragma unroll
    for (int mt = 0; mt < 2; mt++)
        a_off[mt] = ((wm + mt * 16 + (lane & 15)) * (BKt + 4) + (lane >> 4) * 4) * 4;
    #pragma unroll
    for (int pr = 0; pr < 2; pr++)
        b_off[pr] = ((wn + pr * 16 + (lane & 7) + ((lane & 16) ? 8 : 0)) * BC +
                     ((lane & 8) ? 4 : 0)) * 4;

    auto load_tile = [&](int s, int k0) {
        #pragma unroll
        for (int p = 0; p < 2; p++) {
            if (!TA) {
                #pragma unroll
                for (int j = 0; j < 2; j++) {
                    int idx = t + j * 256;
                    int row = idx >> 2;
                    int col = (idx & 3) * 4;
                    cp16(&As[s][p][row][col], Abp[p] + (size_t)(bm + row) * K + k0 + col);
                }
            } else {
                #pragma unroll
                for (int j = 0; j < 2; j++) {
                    int idx = t + j * 256;
                    int row = idx >> 5;
                    int col = (idx & 31) * 4;
                    cp16(&As[s][p][row][col], Abp[p] + (size_t)(k0 + row) * M + bm + col);
                }
            }
            {
                int row = t >> 2;
                int col = (t & 3) * 4;
                cp16(&Bs[s][p][row][col], Bbp[p] + (size_t)(bn + row) * K + k0 + col);
            }
        }
    };

    int nk = K / BKt;
    load_tile(0, 0);
    asm volatile("cp.async.commit_group;");
    load_tile(1, BKt);
    asm volatile("cp.async.commit_group;");

    for (int kt = 0; kt < nk; kt++) {
        int s = kt % 3;
        if (kt < nk - 1) asm volatile("cp.async.wait_group 1;");
        else             asm volatile("cp.async.wait_group 0;");
        __syncthreads();
        if (kt + 2 < nk) {
            load_tile((kt + 2) % 3, (kt + 2) * BKt);
            asm volatile("cp.async.commit_group;");
        }

        uint32_t aB[2], bB[2];
        aB[0] = (uint32_t)__cvta_generic_to_shared(&As[s][0][0][0]);
        aB[1] = (uint32_t)__cvta_generic_to_shared(&As[s][1][0][0]);
        bB[0] = (uint32_t)__cvta_generic_to_shared(&Bs[s][0][0][0]);
        bB[1] = (uint32_t)__cvta_generic_to_shared(&Bs[s][1][0][0]);

        #pragma unroll
        for (int kk = 0; kk < BKt; kk += 8) {
            uint32_t ah[2][4], al[2][4], bh[4][2], bl[4][2];
            if (!TA) {
                #pragma unroll
                for (int mt = 0; mt < 2; mt++) {
                    LDSM4(ah[mt][0], ah[mt][1], ah[mt][2], ah[mt][3],
                          aB[0] + a_off[mt] + kk * 4);
                    LDSM4(al[mt][0], al[mt][1], al[mt][2], al[mt][3],
                          aB[1] + a_off[mt] + kk * 4);
                }
            } else {
                #pragma unroll
                for (int mt = 0; mt < 2; mt++) {
                    int m0 = wm + mt * 16 + gid;
                    ah[mt][0] = __float_as_uint(As[s][0][kk + tig][m0]);
                    ah[mt][1] = __float_as_uint(As[s][0][kk + tig][m0 + 8]);
                    ah[mt][2] = __float_as_uint(As[s][0][kk + tig + 4][m0]);
                    ah[mt][3] = __float_as_uint(As[s][0][kk + tig + 4][m0 + 8]);
                    al[mt][0] = __float_as_uint(As[s][1][kk + tig][m0]);
                    al[mt][1] = __float_as_uint(As[s][1][kk + tig][m0 + 8]);
                    al[mt][2] = __float_as_uint(As[s][1][kk + tig + 4][m0]);
                    al[mt][3] = __float_as_uint(As[s][1][kk + tig + 4][m0 + 8]);
                }
            }
            LDSM4(bh[0][0], bh[0][1], bh[1][0], bh[1][1], bB[0] + b_off[0] + kk * 4);
            LDSM4(bh[2][0], bh[2][1], bh[3][0], bh[3][1], bB[0] + b_off[1] + kk * 4);
            LDSM4(bl[0][0], bl[0][1], bl[1][0], bl[1][1], bB[1] + b_off[0] + kk * 4);
            LDSM4(bl[2][0], bl[2][1], bl[3][0], bl[3][1], bB[1] + b_off[1] + kk * 4);

            #pragma unroll
            for (int mt = 0; mt < 2; mt++)
                #pragma unroll
                for (int nt = 0; nt < 4; nt++) {
                    MMA_TF32(acc[mt][nt], al[mt], bh[nt]);
                    MMA_TF32(acc[mt][nt], ah[mt], bl[nt]);
                    MMA_TF32(acc[mt][nt], ah[mt], bh[nt]);
                }
        }
        __syncthreads();
    }

    float* Cb  = C  ? C  + (size_t)blockIdx.z * sC : nullptr;
    float* Chb = Ch ? Ch + (size_t)blockIdx.z * sC : nullptr;
    float* Clb = Cl ? Cl + (size_t)blockIdx.z * sC : nullptr;
    #pragma unroll
    for (int mt = 0; mt < 2; mt++) {
        int row0 = bm + wm + mt * 16 + gid;
        #pragma unroll
        for (int nt = 0; nt < 4; nt++) {
            int col = bn + wn + nt * 8 + tig * 2;
            float bx = bias ? bias[col] : 0.0f;
            float by = bias ? bias[col + 1] : 0.0f;
            float v00 = acc[mt][nt][0] + bx, v01 = acc[mt][nt][1] + by;
            float v10 = acc[mt][nt][2] + bx, v11 = acc[mt][nt][3] + by;
            if (Cb) {
                *reinterpret_cast<float2*>(&Cb[(size_t)row0 * N + col]) = make_float2(v00, v01);
                *reinterpret_cast<float2*>(&Cb[(size_t)(row0 + 8) * N + col]) = make_float2(v10, v11);
            }
            if (Chb) {
                uint32_t h, l;
                if (!transC) {
                    float2 h0, l0, h1, l1;
                    tf32_split_u(v00, h, l); h0.x = __uint_as_float(h); l0.x = __uint_as_float(l);
                    tf32_split_u(v01, h, l); h0.y = __uint_as_float(h); l0.y = __uint_as_float(l);
                    tf32_split_u(v10, h, l); h1.x = __uint_as_float(h); l1.x = __uint_as_float(l);
                    tf32_split_u(v11, h, l); h1.y = __uint_as_float(h); l1.y = __uint_as_float(l);
                    *reinterpret_cast<float2*>(&Chb[(size_t)row0 * N + col]) = h0;
                    *reinterpret_cast<float2*>(&Clb[(size_t)row0 * N + col]) = l0;
                    *reinterpret_cast<float2*>(&Chb[(size_t)(row0 + 8) * N + col]) = h1;
                    *reinterpret_cast<float2*>(&Clb[(size_t)(row0 + 8) * N + col]) = l1;
                } else {
                    // transposed planes: [N][M]
                    tf32_split_u(v00, h, l);
                    Chb[(size_t)col * M + row0] = __uint_as_float(h);
                    Clb[(size_t)col * M + row0] = __uint_as_float(l);
                    tf32_split_u(v01, h, l);
                    Chb[(size_t)(col + 1) * M + row0] = __uint_as_float(h);
                    Clb[(size_t)(col + 1) * M + row0] = __uint_as_float(l);
                    tf32_split_u(v10, h, l);
                    Chb[(size_t)col * M + row0 + 8] = __uint_as_float(h);
                    Clb[(size_t)col * M + row0 + 8] = __uint_as_float(l);
                    tf32_split_u(v11, h, l);
                    Chb[(size_t)(col + 1) * M + row0 + 8] = __uint_as_float(h);
                    Clb[(size_t)(col + 1) * M + row0 + 8] = __uint_as_float(l);
                }
            }
        }
    }
}

// ------------------------- gc2 & gc3 fused SIMT GEMM -----------------------
__global__ void gc23_kernel(const float* __restrict__ A, const float* __restrict__ B2,
                            const float* __restrict__ B3, float* __restrict__ C2,
                            float* __restrict__ C3) {
    __shared__ __align__(16) float As[16][64];
    __shared__ __align__(16) float Bs[16][64];
    int bm = blockIdx.x * 64;
    int t = threadIdx.x, tx = t & 15, ty = t >> 4;
    float acc[4][4] = {};
    for (int k0 = 0; k0 < H1d; k0 += 16) {
        #pragma unroll
        for (int j = 0; j < 4; j++) {
            int li = t + j * 256;
            int r = li >> 4, c = li & 15;
            As[c][r] = A[(size_t)(bm + r) * H1d + k0 + c];
            int rb = li >> 6, cb = li & 63;
            Bs[rb][cb] = (cb < 32) ? B2[(k0 + rb) * H2d + cb]
                                   : B3[(k0 + rb) * H2d + cb - 32];
        }
        __syncthreads();
        #pragma unroll
        for (int k = 0; k < 16; k++) {
            float4 a4 = *reinterpret_cast<const float4*>(&As[k][ty << 2]);
            float4 b4 = *reinterpret_cast<const float4*>(&Bs[k][tx << 2]);
            float a[4] = {a4.x, a4.y, a4.z, a4.w};
            float b[4] = {b4.x, b4.y, b4.z, b4.w};
            #pragma unroll
            for (int u = 0; u < 4; u++)
                #pragma unroll
                for (int v = 0; v < 4; v++)
                    acc[u][v] += a[u] * b[v];
        }
        __syncthreads();
    }
    #pragma unroll
    for (int u = 0; u < 4; u++) {
        int row = bm + (ty << 2) + u;
        #pragma unroll
        for (int v = 0; v < 4; v++) {
            int col = (tx << 2) + v;
            if (col < 32) C2[(size_t)row * H2d + col] = acc[u][v];
            else          C3[(size_t)row * H2d + col - 32] = acc[u][v];
        }
    }
}

// ------------------------- f/g projections ---------------------------------
__global__ void fg_kernel(const float* __restrict__ Wh, const float* __restrict__ asrc,
                          const float* __restrict__ adst, float* __restrict__ f,
                          float* __restrict__ g, int n) {
    int gw = (blockIdx.x * blockDim.x + threadIdx.x) >> 5;
    int lane = threadIdx.x & 31;
    if (gw >= NHd * n) return;
    int h = gw / n, i = gw - h * n;
    const float* w  = Wh + ((size_t)h * n + i) * Dd;
    const float* as = asrc + h * Dd;
    const float* ad = adst + h * Dd;
    float accf = 0.0f, accg = 0.0f;
    #pragma unroll
    for (int c = 0; c < Dd / 32; c++) {
        float v = w[lane + 32 * c];
        accf += v * as[lane + 32 * c];
        accg += v * ad[lane + 32 * c];
    }
    #pragma unroll
    for (int o = 16; o; o >>= 1) {
        accf += __shfl_down_sync(0xffffffffu, accf, o);
        accg += __shfl_down_sync(0xffffffffu, accg, o);
    }
    if (lane == 0) { f[gw] = accf; g[gw] = accg; }
}

// ------------------------- warp-per-(i,h) GAT attention --------------------
__global__ void __launch_bounds__(256) gat_attn_warp_kernel(
    const float* __restrict__ Wh, const float* __restrict__ f,
    const float* __restrict__ g, const int* __restrict__ nbr,
    const int* __restrict__ cnt, float* __restrict__ hcat_h,
    float* __restrict__ hcat_l, int n) {
    int w = threadIdx.x >> 5, lane = threadIdx.x & 31;
    int gw = blockIdx.x * 8 + w;
    int i = gw >> 2, h = gw & 3;
    __shared__ int   sj[8][CAP];
    __shared__ float sw[8][CAP];
    int c = cnt[i];
    const int* jb = nbr + i * CAP;
    float fi = f[h * n + i];
    float m = -1e30f;
    for (int k = lane; k < c; k += 32) {
        int j = jb[k];
        sj[w][k] = j;
        float s = fi + g[h * n + j];
        s = (s >= 0.0f) ? s : LRELU_ALPHA * s;
        sw[w][k] = s;
        m = fmaxf(m, s);
    }
    #pragma unroll
    for (int o = 16; o; o >>= 1) m = fmaxf(m, __shfl_xor_sync(0xffffffffu, m, o));
    __syncwarp();
    float sum = 0.0f;
    for (int k = lane; k < c; k += 32) {
        float e = expf(sw[w][k] - m);
        sw[w][k] = e;
        sum += e;
    }
    #pragma unroll
    for (int o = 16; o; o >>= 1) sum += __shfl_xor_sync(0xffffffffu, sum, o);
    float dinv = 1.0f / sum;
    __syncwarp();
    const float* base = Wh + (size_t)h * n * Dd;
    float acc[8] = {};
    int k = 0;
    for (; k + 2 <= c; k += 2) {
        float w0 = sw[w][k], w1 = sw[w][k + 1];
        const float* r0 = base + (size_t)sj[w][k] * Dd + lane;
        const float* r1 = base + (size_t)sj[w][k + 1] * Dd + lane;
        #pragma unroll
        for (int ch = 0; ch < 8; ch++) {
            acc[ch] += w0 * __ldg(r0 + ch * 32);
            acc[ch] += w1 * __ldg(r1 + ch * 32);
        }
    }
    if (k < c) {
        float w0 = sw[w][k];
        const float* r0 = base + (size_t)sj[w][k] * Dd + lane;
        #pragma unroll
        for (int ch = 0; ch < 8; ch++) acc[ch] += w0 * __ldg(r0 + ch * 32);
    }
    size_t obase = (size_t)i * (NHd * Dd) + h * Dd + lane;
    #pragma unroll
    for (int ch = 0; ch < 8; ch++) {
        float v = acc[ch] * dinv;
        v = (v > 0.0f) ? v : expm1f(v);
        split_store(v, hcat_h, hcat_l, obase + ch * 32);
    }
}

// ------------------------- gated fusion elementwise ------------------------
__global__ void fuse_kernel(const float* __restrict__ a, const float* __restrict__ b,
                            float* __restrict__ out_h, float* __restrict__ out_l,
                            int total) {
    int idx = blockIdx.x * blockDim.x + threadIdx.x;
    if (idx < total) {
        float ca = a[idx], cb = b[idx];
        float z = 1.0f / (1.0f + expf(-(ca + cb)));
        split_store(z * ca + (1.0f - z) * cb, out_h, out_l, idx);
    }
}

// ------------------------- sparse adj @ X, optional ReLU -------------------
__global__ void spmm_kernel(const int* __restrict__ nbr, const float* __restrict__ val,
                            const int* __restrict__ cnt, const float* __restrict__ X,
                            float* __restrict__ Y, int ncols, int do_relu) {
    int i = blockIdx.x;
    int t = threadIdx.x;
    int c = cnt[i];
    const int* jb = nbr + i * CAP;
    const float* vb = val + i * CAP;
    float a0 = 0.0f, a1 = 0.0f, a2 = 0.0f, a3 = 0.0f;
    int k = 0;
    for (; k + 4 <= c; k += 4) {
        a0 += vb[k]     * __ldg(X + (size_t)jb[k]     * ncols + t);
        a1 += vb[k + 1] * __ldg(X + (size_t)jb[k + 1] * ncols + t);
        a2 += vb[k + 2] * __ldg(X + (size_t)jb[k + 2] * ncols + t);
        a3 += vb[k + 3] * __ldg(X + (size_t)jb[k + 3] * ncols + t);
    }
    for (; k < c; k++)
        a0 += vb[k] * __ldg(X + (size_t)jb[k] * ncols + t);
    float acc = (a0 + a1) + (a2 + a3);
    if (do_relu) acc = fmaxf(acc, 0.0f);
    Y[(size_t)i * ncols + t] = acc;
}

// ------------------------- fused mu/logvar spmm ----------------------------
__global__ void spmm2_kernel(const int* __restrict__ nbr, const float* __restrict__ val,
                             const int* __restrict__ cnt, const float* __restrict__ X2,
                             const float* __restrict__ X3, float* __restrict__ mu,
                             float* __restrict__ logvar, float* __restrict__ mu_h,
                             float* __restrict__ mu_l) {
    int i = blockIdx.x;
    int t = threadIdx.x;
    int sel = t >> 5, col = t & 31;
    const float* X = sel ? X3 : X2;
    int c = cnt[i];
    const int* jb = nbr + i * CAP;
    const float* vb = val + i * CAP;
    float a0 = 0.0f, a1 = 0.0f, a2 = 0.0f, a3 = 0.0f;
    int k = 0;
    for (; k + 4 <= c; k += 4) {
        a0 += vb[k]     * __ldg(X + (size_t)jb[k]     * H2d + col);
        a1 += vb[k + 1] * __ldg(X + (size_t)jb[k + 1] * H2d + col);
        a2 += vb[k + 2] * __ldg(X + (size_t)jb[k + 2] * H2d + col);
        a3 += vb[k + 3] * __ldg(X + (size_t)jb[k + 3] * H2d + col);
    }
    for (; k < c; k++)
        a0 += vb[k] * __ldg(X + (size_t)jb[k] * H2d + col);
    float v = (a0 + a1) + (a2 + a3);
    size_t idx = (size_t)i * H2d + col;
    if (sel == 0) {
        mu[idx] = v;
        split_store(v, mu_h, mu_l, idx);
    } else {
        logvar[idx] = v;
    }
}

// ------------------------- host-side launch helpers ------------------------
struct GemmArgs {
    const float *Ah, *Al, *Bh, *Bl, *bias;
    float *C, *Ch, *Cl;
    int transC;
};
static inline void run_nn(GemmArgs a, int M, int N, int K, int batch = 1,
                          size_t sA = 0, size_t sB = 0, size_t sC = 0) {
    dim3 grid(N / BNt, M / BMt, batch);
    mma_gemm_kernel<false><<<grid, 256>>>(a.Ah, a.Al, a.Bh, a.Bl, a.bias,
                                          a.C, a.Ch, a.Cl, a.transC, M, N, K, sA, sB, sC);
}
static inline void run_tn(GemmArgs a, int M, int N, int K) {
    dim3 grid(N / BNt, M / BMt, 1);
    mma_gemm_kernel<true><<<grid, 256>>>(a.Ah, a.Al, a.Bh, a.Bl, a.bias,
                                         a.C, a.Ch, a.Cl, a.transC, M, N, K, 0, 0, 0);
}

#define SYM(p, s) cudaGetSymbolAddress((void**)&p, s)

extern "C" void kernel_launch(void* const* d_in, const int* in_sizes, int n_in,
                              void* d_out, int out_size) {
    const float* x        = (const float*)d_in[0];
    const float* adj      = (const float*)d_in[1];
    const float* t_x      = (const float*)d_in[2];
    const float* t_adj    = (const float*)d_in[3];
    const float* tfidf    = (const float*)d_in[4];
    const float* gat_W    = (const float*)d_in[5];
    const float* gat_asrc = (const float*)d_in[6];
    const float* gat_adst = (const float*)d_in[7];
    const float* gat_fcW  = (const float*)d_in[8];
    const float* gat_fcb  = (const float*)d_in[9];
    const float* t_W      = (const float*)d_in[10];
    const float* t_asrc   = (const float*)d_in[11];
    const float* t_adst   = (const float*)d_in[12];
    const float* t_fcW    = (const float*)d_in[13];
    const float* t_fcb    = (const float*)d_in[14];
    const float* fus_W    = (const float*)d_in[15];
    const float* fus_b    = (const float*)d_in[16];
    const float* gc1_W    = (const float*)d_in[17];
    const float* gc2_W    = (const float*)d_in[18];
    const float* gc3_W    = (const float*)d_in[19];

    float* out    = (float*)d_out;
    float* mu     = out + (size_t)Nn * Nn;
    float* logvar = mu + (size_t)Nn * H2d;

    float *Wh_c, *Wh_t, *f_c, *g_c, *f_t, *g_t, *val_c, *val_t;
    float *concept, *ctext, *tmp1, *h1, *tmp2a, *tmp2b;
    int *nbr_c, *cnt_c, *nbr_t, *cnt_t;
    float *x_h, *x_l, *tx_h, *tx_l, *tf_h, *tf_l;
    float *gatWT_h, *gatWT_l, *tWT_h, *tWT_l, *fcWcT_h, *fcWcT_l, *fcWtT_h, *fcWtT_l;
    float *fusWT_h, *fusWT_l, *gc1WT_h, *gc1WT_l;
    float *hcatc_h, *hcatc_l, *hcatt_h, *hcatt_l, *gtextT_h, *gtextT_l;
    float *fused_h, *fused_l, *fusion_h, *fusion_l, *mu_h, *mu_l;
    SYM(Wh_c, g_Wh_c);  SYM(Wh_t, g_Wh_t);
    SYM(f_c, g_f_c);    SYM(g_c, g_g_c);   SYM(f_t, g_f_t);  SYM(g_t, g_g_t);
    SYM(nbr_c, g_nbr_c); SYM(val_c, g_val_c); SYM(cnt_c, g_cnt_c);
    SYM(nbr_t, g_nbr_t); SYM(val_t, g_val_t); SYM(cnt_t, g_cnt_t);
    SYM(concept, g_concept); SYM(ctext, g_ctext);
    SYM(tmp1, g_tmp1); SYM(h1, g_h1); SYM(tmp2a, g_tmp2a); SYM(tmp2b, g_tmp2b);
    SYM(x_h, g_x_h);   SYM(x_l, g_x_l);  SYM(tx_h, g_tx_h); SYM(tx_l, g_tx_l);
    SYM(tf_h, g_tf_h); SYM(tf_l, g_tf_l);
    SYM(gatWT_h, g_gatWT_h); SYM(gatWT_l, g_gatWT_l);
    SYM(tWT_h, g_tWT_h);     SYM(tWT_l, g_tWT_l);
    SYM(fcWcT_h, g_fcWcT_h); SYM(fcWcT_l, g_fcWcT_l);
    SYM(fcWtT_h, g_fcWtT_h); SYM(fcWtT_l, g_fcWtT_l);
    SYM(fusWT_h, g_fusWT_h); SYM(fusWT_l, g_fusWT_l);
    SYM(gc1WT_h, g_gc1WT_h); SYM(gc1WT_l, g_gc1WT_l);
    SYM(hcatc_h, g_hcatc_h); SYM(hcatc_l, g_hcatc_l);
    SYM(hcatt_h, g_hcatt_h); SYM(hcatt_l, g_hcatt_l);
    SYM(gtextT_h, g_gtextT_h); SYM(gtextT_l, g_gtextT_l);
    SYM(fused_h, g_fused_h); SYM(fused_l, g_fused_l);
    SYM(fusion_h, g_fusion_h); SYM(fusion_l, g_fusion_l);
    SYM(mu_h, g_mu_h); SYM(mu_l, g_mu_l);

    // 0a) split A-side inputs (no transpose)
    {
        SplitJobs3 jobs;
        jobs.j[0] = { x,     x_h,  x_l,  Nn * Dd / 4 };
        jobs.j[1] = { t_x,   tx_h, tx_l, Tt * Dd / 4 };
        jobs.j[2] = { tfidf, tf_h, tf_l, Tt * Nn / 4 };
        split_all_kernel<<<dim3(160, 3), 256>>>(jobs);
    }
    // 0b) transpose+split all B-side weights -> [N,K]
    {
        TJobs6 jobs;
        jobs.j[0] = { gat_W,   gatWT_h, gatWT_l, Dd, Dd, NHd };
        jobs.j[1] = { t_W,     tWT_h,   tWT_l,   Dd, Dd, NHd };
        jobs.j[2] = { gat_fcW, fcWcT_h, fcWcT_l, NHd * Dd, Dd, 1 };
        jobs.j[3] = { t_fcW,   fcWtT_h, fcWtT_l, NHd * Dd, Dd, 1 };
        jobs.j[4] = { fus_W,   fusWT_h, fusWT_l, Dd, Dd, 1 };
        jobs.j[5] = { gc1_W,   gc1WT_h, gc1WT_l, Dd, H1d, 1 };
        transpose_split_kernel<<<dim3(64, 6, 4), dim3(32, 8)>>>(jobs);
    }

    // 1) adjacency -> CSR
    build_csr_kernel<<<Nn, 256>>>(adj, Nn, nbr_c, val_c, cnt_c);
    build_csr_kernel<<<Tt, 256>>>(t_adj, Tt, nbr_t, val_t, cnt_t);

    // 2) per-head Wh = x @ W[h]  (batched over heads)
    run_nn({x_h, x_l, gatWT_h, gatWT_l, nullptr, Wh_c, nullptr, nullptr, 0},
           Nn, Dd, Dd, NHd, 0, (size_t)Dd * Dd, (size_t)Nn * Dd);
    run_nn({tx_h, tx_l, tWT_h, tWT_l, nullptr, Wh_t, nullptr, nullptr, 0},
           Tt, Dd, Dd, NHd, 0, (size_t)Dd * Dd, (size_t)Tt * Dd);

    // 3) attention projections f,g
    fg_kernel<<<(NHd * Nn * 32 + 255) / 256, 256>>>(Wh_c, gat_asrc, gat_adst, f_c, g_c, Nn);
    fg_kernel<<<(NHd * Tt * 32 + 255) / 256, 256>>>(Wh_t, t_asrc, t_adst, f_t, g_t, Tt);

    // 4) sparse attention + aggregation + ELU -> hcat hi/lo planes
    gat_attn_warp_kernel<<<Nn * NHd / 8, 256>>>(Wh_c, f_c, g_c, nbr_c, cnt_c,
                                                hcatc_h, hcatc_l, Nn);
    gat_attn_warp_kernel<<<Tt * NHd / 8, 256>>>(Wh_t, f_t, g_t, nbr_t, cnt_t,
                                                hcatt_h, hcatt_l, Tt);

    // 5) output fc per graph (text output split+transposed for next GEMM's B)
    run_nn({hcatc_h, hcatc_l, fcWcT_h, fcWcT_l, gat_fcb, concept, nullptr, nullptr, 0},
           Nn, Dd, NHd * Dd);
    run_nn({hcatt_h, hcatt_l, fcWtT_h, fcWtT_l, t_fcb, nullptr, gtextT_h, gtextT_l, 1},
           Tt, Dd, NHd * Dd);

    // 6) c_text = tfidf^T @ gat_text  (A: TA planes [T,N]; B: gtextT [D,T])
    run_tn({tf_h, tf_l, gtextT_h, gtextT_l, nullptr, ctext, nullptr, nullptr, 0},
           Nn, Dd, Tt);

    // 7) gated fusion + fc
    fuse_kernel<<<(Nn * Dd + 255) / 256, 256>>>(concept, ctext, fused_h, fused_l, Nn * Dd);
    run_nn({fused_h, fused_l, fusWT_h, fusWT_l, fus_b, nullptr, fusion_h, fusion_l, 0},
           Nn, Dd, Dd);

    // 8) GCN encoder
    run_nn({fusion_h, fusion_l, gc1WT_h, gc1WT_l, nullptr, tmp1, nullptr, nullptr, 0},
           Nn, H1d, Dd);
    spmm_kernel<<<Nn, H1d>>>(nbr_c, val_c, cnt_c, tmp1, h1, H1d, 1);

    gc23_kernel<<<Nn / 64, 256>>>(h1, gc2_W, gc3_W, tmp2a, tmp2b);
    spmm2_kernel<<<Nn, 64>>>(nbr_c, val_c, cnt_c, tmp2a, tmp2b, mu, logvar, mu_h, mu_l);

    // 9) recon = mu @ mu^T  (mu planes are [4096,32]: valid A [M,K] and B [N,K])
    run_nn({mu_h, mu_l, mu_h, mu_l, nullptr, out, nullptr, nullptr, 0}, Nn, Nn, H2d);
}